// round 8
// baseline (speedup 1.0000x reference)
#include <cuda_runtime.h>
#include <cuda_pipeline.h>

// Fused 2-layer MLP, HBM-streaming bound (1 GiB input read once).
//   h[b,f]  = relu(sum_i in[b,f,i]*W1[f,i] + b1[f])   B=8192,F=256,I=128
//   out[b,o]= relu(sum_f h[b,f]*W2[o,f] + b2[o])      O=128
//
// R6 -> R7: dynamic work stealing (global pair counter, grabbed one pair
// ahead so ATOMG latency is fully hidden) to kill the static-partition
// between-SM spread (~1.10 floor). cp.async ring + 2-batch pairs unchanged.

#define THREADS 512
#define DEPTH 2

constexpr int Bn = 8192;
constexpr int Fn = 256;
constexpr int On = 128;
constexpr int NPAIRS = Bn / 2;   // 4096

// SMEM layout (floats):
constexpr int SM_W1   = 0;                                  // 32768 floats
constexpr int SM_RING = 32768;                              // DEPTH*4*512 float4 = 64KB
constexpr int SM_H    = SM_RING + DEPTH * 4 * THREADS * 4;  // 512 floats
constexpr int SM_PART = SM_H + 512;                         // 1024 floats
constexpr int SM_B1   = SM_PART + 1024;                     // 256
constexpr int SM_B2   = SM_B1 + 256;                        // 128
constexpr int SM_CTL  = SM_B2 + 128;                        // 4 ints (pair queue comm)
constexpr int SM_FLOATS = SM_CTL + 4;
constexpr int SMEM_BYTES = SM_FLOATS * 4;                   // ~204KB

__device__ unsigned g_pair_ctr;

__global__ void reset_ctr_kernel() { g_pair_ctr = 0u; }

__global__ __launch_bounds__(THREADS, 1)
void mlp_fused_kernel(const float* __restrict__ in,
                      const float* __restrict__ W1,
                      const float* __restrict__ b1,
                      const float* __restrict__ W2,
                      const float* __restrict__ b2,
                      float* __restrict__ out)
{
    extern __shared__ float smem[];
    float4* w1s4   = reinterpret_cast<float4*>(smem + SM_W1);
    float4* ringf4 = reinterpret_cast<float4*>(smem + SM_RING);
    float*  hs     = smem + SM_H;
    float*  part   = smem + SM_PART;
    float*  b1s    = smem + SM_B1;
    float*  b2s    = smem + SM_B2;
    int*    ctl    = reinterpret_cast<int*>(smem + SM_CTL);

    const int tid = threadIdx.x;

    // stage-1 geometry: warp owns 16 feature rows; 4-row x 8-lane groups
    const int w   = tid >> 5;
    const int l   = tid & 31;
    const int sub = l >> 3;
    const int c   = l & 7;
    const int rowBase = w * 16;

    const float4* in4 = reinterpret_cast<const float4*>(in);

    // issue one group (batch, chunk) into ring slot 'slot' via cp.async.cg
    auto issue_group = [&](int batch, int chunk, int slot) {
        int base = (batch * Fn + rowBase + chunk * 4 + sub) * 32 + c;
        float4* dst = ringf4 + slot * (4 * THREADS) + tid;
        #pragma unroll
        for (int k = 0; k < 4; k++)
            __pipeline_memcpy_async(dst + k * THREADS, in4 + base + 8 * k, 16);
        __pipeline_commit();
    };

    // ---- grab first two pairs ----
    if (tid == 0) {
        ctl[0] = (int)atomicAdd(&g_pair_ctr, 1u);   // cur
        ctl[1] = (int)atomicAdd(&g_pair_ctr, 1u);   // nxt
    }
    __syncthreads();
    int curP = ctl[0];
    int nxtP = ctl[1];

    // prime: groups 0,1 (chunks 0,1 of cur pair's batch A)
    {
        int bA = (curP < NPAIRS) ? curP * 2 : 0;
        issue_group(bA, 0, 0);
        issue_group(bA, 1, 1);
    }

    // ---- one-time loads ----
    {
        const float4* W1g = reinterpret_cast<const float4*>(W1);
        #pragma unroll 4
        for (int i = tid; i < Fn * 32; i += THREADS) w1s4[i] = W1g[i];
        for (int i = tid; i < Fn; i += THREADS) b1s[i] = b1[i];
        if (tid < On) b2s[tid] = b2[tid];
    }

    // W2 slice in registers
    const int o = tid & 127;
    const int p = tid >> 7;
    float w2r[64];
    {
        const float4* W2g = reinterpret_cast<const float4*>(W2);
        #pragma unroll
        for (int j = 0; j < 16; j++) {
            float4 v = W2g[o * 64 + p * 16 + j];
            w2r[4*j+0] = v.x; w2r[4*j+1] = v.y;
            w2r[4*j+2] = v.z; w2r[4*j+3] = v.w;
        }
    }
    __syncthreads();

    while (curP < NPAIRS) {
        const int bA = curP * 2;
        const int bB = bA + 1;
        const int nA = (nxtP < NPAIRS) ? nxtP * 2 : 0;   // dummy clamp

        // grab pair-after-next EARLY: latency hidden under the 8 steps
        unsigned newP = 0;
        if (tid == THREADS - 1) newP = atomicAdd(&g_pair_ctr, 1u);

        // ---- stage 1: 8 groups (2 batches) ----
        #pragma unroll
        for (int g = 0; g < 8; g++) {
            __pipeline_wait_prior(DEPTH - 1);
            const int slot = g & 1;
            const float4* src = ringf4 + slot * (4 * THREADS) + tid;
            float4 x0 = src[0], x1 = src[THREADS], x2 = src[2*THREADS], x3 = src[3*THREADS];

            // refill this slot with group g+2 (crosses into next pair at g>=6)
            if (g < 6) {
                const int t = g + 2;
                issue_group((t < 4) ? bA : bB, t & 3, slot);
            } else {
                issue_group(nA, g - 6, slot);
            }

            const int r = rowBase + (g & 3) * 4 + sub;
            const float4* wrow = &w1s4[r * 32 + c];
            float4 w0 = wrow[0], w1v = wrow[8], w2v = wrow[16], w3 = wrow[24];
            float a0 = 0.f, a1 = 0.f;
            a0 = fmaf(x0.x, w0.x, a0);  a1 = fmaf(x0.y, w0.y, a1);
            a0 = fmaf(x0.z, w0.z, a0);  a1 = fmaf(x0.w, w0.w, a1);
            a0 = fmaf(x1.x, w1v.x, a0); a1 = fmaf(x1.y, w1v.y, a1);
            a0 = fmaf(x1.z, w1v.z, a0); a1 = fmaf(x1.w, w1v.w, a1);
            a0 = fmaf(x2.x, w2v.x, a0); a1 = fmaf(x2.y, w2v.y, a1);
            a0 = fmaf(x2.z, w2v.z, a0); a1 = fmaf(x2.w, w2v.w, a1);
            a0 = fmaf(x3.x, w3.x, a0);  a1 = fmaf(x3.y, w3.y, a1);
            a0 = fmaf(x3.z, w3.z, a0);  a1 = fmaf(x3.w, w3.w, a1);
            float s = a0 + a1;
            s += __shfl_xor_sync(0xffffffffu, s, 4);
            s += __shfl_xor_sync(0xffffffffu, s, 2);
            s += __shfl_xor_sync(0xffffffffu, s, 1);
            if (c == 0) hs[((g & 4) ? 256 : 0) + r] = fmaxf(s + b1s[r], 0.f);
        }
        __syncthreads();   // h (both batches) ready

        // ---- stage 2 ----
        {
            const float4* hqA = reinterpret_cast<const float4*>(hs + p * 64);
            const float4* hqB = reinterpret_cast<const float4*>(hs + 256 + p * 64);
            float A0=0.f, A1=0.f, B0=0.f, B1=0.f;
            #pragma unroll
            for (int j = 0; j < 16; j++) {
                float4 ha = hqA[j], hb = hqB[j];   // warp-broadcast LDS
                A0 = fmaf(ha.x, w2r[4*j+0], A0);
                A1 = fmaf(ha.y, w2r[4*j+1], A1);
                A0 = fmaf(ha.z, w2r[4*j+2], A0);
                A1 = fmaf(ha.w, w2r[4*j+3], A1);
                B0 = fmaf(hb.x, w2r[4*j+0], B0);
                B1 = fmaf(hb.y, w2r[4*j+1], B1);
                B0 = fmaf(hb.z, w2r[4*j+2], B0);
                B1 = fmaf(hb.w, w2r[4*j+3], B1);
            }
            part[p * 128 + o]       = A0 + A1;
            part[512 + p * 128 + o] = B0 + B1;
        }
        if (tid == THREADS - 1) ctl[2] = (int)newP;   // publish pair-after-next
        __syncthreads();   // partials (and ctl[2]) ready

        // ---- combine + store ----
        if (tid < 256) {
            const int oo  = tid & 127;
            const int off = (tid & 128) ? 512 : 0;
            const int bb  = (tid & 128) ? bB : bA;
            float v = part[off + oo] + part[off + 128 + oo] +
                      part[off + 256 + oo] + part[off + 384 + oo] + b2s[oo];
            out[bb * On + oo] = fmaxf(v, 0.f);
        }
        curP = nxtP;
        nxtP = ctl[2];
    }
    __pipeline_wait_prior(0);   // drain dummy tail groups
}

extern "C" void kernel_launch(void* const* d_in, const int* in_sizes, int n_in,
                              void* d_out, int out_size)
{
    const float* in_ = (const float*)d_in[0];
    const float* W1  = (const float*)d_in[1];
    const float* b1  = (const float*)d_in[2];
    const float* W2  = (const float*)d_in[3];
    const float* b2  = (const float*)d_in[4];
    float* out       = (float*)d_out;

    int nsm = 0;
    if (cudaDeviceGetAttribute(&nsm, cudaDevAttrMultiProcessorCount, 0) != cudaSuccess
        || nsm <= 0) {
        nsm = 148;
    }

    cudaFuncSetAttribute(mlp_fused_kernel,
                         cudaFuncAttributeMaxDynamicSharedMemorySize, SMEM_BYTES);

    reset_ctr_kernel<<<1, 1>>>();
    mlp_fused_kernel<<<nsm, THREADS, SMEM_BYTES>>>(in_, W1, b1, W2, b2, out);
}

// round 17
// speedup vs baseline: 1.1254x; 1.1254x over previous
#include <cuda_runtime.h>
#include <cuda_pipeline.h>

// Fused 2-layer MLP, HBM-streaming bound (1 GiB input read once).
//   h[b,f]  = relu(sum_i in[b,f,i]*W1[f,i] + b1[f])   B=8192,F=256,I=128
//   out[b,o]= relu(sum_f h[b,f]*W2[o,f] + b2[o])      O=128
//
// R8 -> R9: REVERT work stealing (regressed: L1tex 80%, DRAM 73%).
// Back to R6 static partition + cp.async ring; widen super-iteration
// 2 -> 4 batches (16 stream steps per barrier pair, ~30 barriers/block).

#define THREADS 512
#define DEPTH 2

constexpr int Bn = 8192;
constexpr int Fn = 256;
constexpr int On = 128;

// SMEM layout (floats):
constexpr int SM_W1   = 0;                                  // 32768
constexpr int SM_RING = 32768;                              // 16384 floats (64KB)
constexpr int SM_H    = SM_RING + DEPTH * 4 * THREADS * 4;  // 49152, 1024 floats
constexpr int SM_PART = SM_H + 1024;                        // 50176, 2048 floats
constexpr int SM_B1   = SM_PART + 2048;                     // 52224
constexpr int SM_B2   = SM_B1 + 256;                        // 52480
constexpr int SM_FLOATS = SM_B2 + 128;                      // 52608
constexpr int SMEM_BYTES = SM_FLOATS * 4;                   // 210,432 B

__global__ __launch_bounds__(THREADS, 1)
void mlp_fused_kernel(const float* __restrict__ in,
                      const float* __restrict__ W1,
                      const float* __restrict__ b1,
                      const float* __restrict__ W2,
                      const float* __restrict__ b2,
                      float* __restrict__ out)
{
    extern __shared__ float smem[];
    float4* w1s4   = reinterpret_cast<float4*>(smem + SM_W1);
    float4* ringf4 = reinterpret_cast<float4*>(smem + SM_RING);
    float*  hs     = smem + SM_H;
    float*  part   = smem + SM_PART;
    float*  b1s    = smem + SM_B1;
    float*  b2s    = smem + SM_B2;

    const int tid  = threadIdx.x;
    const int grid = gridDim.x;
    const int b0   = blockIdx.x;

    const int w   = tid >> 5;
    const int l   = tid & 31;
    const int sub = l >> 3;
    const int c   = l & 7;
    const int rowBase = w * 16;

    const float4* in4 = reinterpret_cast<const float4*>(in);

    // flat group index sidx: batch = b0 + (sidx>>2)*grid, chunk = sidx&3
    auto issue_group = [&](int sidx) {
        int bi = b0 + (sidx >> 2) * grid;
        if (bi >= Bn) bi = b0;       // clamped dummy past the end (value unused)
        int chunk = sidx & 3;
        int base = (bi * Fn + rowBase + chunk * 4 + sub) * 32 + c;
        float4* dst = ringf4 + (sidx & (DEPTH - 1)) * (4 * THREADS) + tid;
        #pragma unroll
        for (int k = 0; k < 4; k++)
            __pipeline_memcpy_async(dst + k * THREADS, in4 + base + 8 * k, 16);
        __pipeline_commit();
    };

    #pragma unroll
    for (int t = 0; t < DEPTH; t++) issue_group(t);

    // ---- one-time loads ----
    {
        const float4* W1g = reinterpret_cast<const float4*>(W1);
        #pragma unroll 4
        for (int i = tid; i < Fn * 32; i += THREADS) w1s4[i] = W1g[i];
        for (int i = tid; i < Fn; i += THREADS) b1s[i] = b1[i];
        if (tid < On) b2s[tid] = b2[tid];
    }

    const int o = tid & 127;
    const int p = tid >> 7;
    float w2r[64];
    {
        const float4* W2g = reinterpret_cast<const float4*>(W2);
        #pragma unroll
        for (int j = 0; j < 16; j++) {
            float4 v = W2g[o * 64 + p * 16 + j];
            w2r[4*j+0] = v.x; w2r[4*j+1] = v.y;
            w2r[4*j+2] = v.z; w2r[4*j+3] = v.w;
        }
    }
    __syncthreads();

    auto step = [&](int sidx, int hoff) {
        __pipeline_wait_prior(DEPTH - 1);
        const float4* src = ringf4 + (sidx & (DEPTH - 1)) * (4 * THREADS) + tid;
        float4 x0 = src[0], x1 = src[THREADS], x2 = src[2*THREADS], x3 = src[3*THREADS];
        issue_group(sidx + DEPTH);

        const int r = rowBase + (sidx & 3) * 4 + sub;
        const float4* wrow = &w1s4[r * 32 + c];
        float4 w0 = wrow[0], w1v = wrow[8], w2v = wrow[16], w3 = wrow[24];
        float a0 = 0.f, a1 = 0.f;
        a0 = fmaf(x0.x, w0.x, a0);  a1 = fmaf(x0.y, w0.y, a1);
        a0 = fmaf(x0.z, w0.z, a0);  a1 = fmaf(x0.w, w0.w, a1);
        a0 = fmaf(x1.x, w1v.x, a0); a1 = fmaf(x1.y, w1v.y, a1);
        a0 = fmaf(x1.z, w1v.z, a0); a1 = fmaf(x1.w, w1v.w, a1);
        a0 = fmaf(x2.x, w2v.x, a0); a1 = fmaf(x2.y, w2v.y, a1);
        a0 = fmaf(x2.z, w2v.z, a0); a1 = fmaf(x2.w, w2v.w, a1);
        a0 = fmaf(x3.x, w3.x, a0);  a1 = fmaf(x3.y, w3.y, a1);
        a0 = fmaf(x3.z, w3.z, a0);  a1 = fmaf(x3.w, w3.w, a1);
        float s = a0 + a1;
        s += __shfl_xor_sync(0xffffffffu, s, 4);
        s += __shfl_xor_sync(0xffffffffu, s, 2);
        s += __shfl_xor_sync(0xffffffffu, s, 1);
        if (c == 0) hs[hoff + r] = fmaxf(s + b1s[r], 0.f);
    };

    int s = 0;
    int b = b0;

    // ---- full 4-batch super-iterations ----
    while (b + 3 * grid < Bn) {
        #pragma unroll
        for (int g = 0; g < 16; g++) {
            step(s, (g >> 2) * 256);
            s++;
        }
        __syncthreads();   // h (4 batches) ready

        #pragma unroll
        for (int q = 0; q < 4; q++) {
            const float4* hq = reinterpret_cast<const float4*>(hs + q * 256 + p * 64);
            float A0 = 0.f, A1 = 0.f;
            #pragma unroll
            for (int j = 0; j < 16; j++) {
                float4 hv = hq[j];    // warp-broadcast LDS
                A0 = fmaf(hv.x, w2r[4*j+0], A0);
                A1 = fmaf(hv.y, w2r[4*j+1], A1);
                A0 = fmaf(hv.z, w2r[4*j+2], A0);
                A1 = fmaf(hv.w, w2r[4*j+3], A1);
            }
            part[q * 512 + p * 128 + o] = A0 + A1;
        }
        __syncthreads();   // partials ready

        {
            const int q   = tid >> 7;
            const int oo  = tid & 127;
            const int off = q * 512;
            const int bb  = b + q * grid;
            float v = part[off + oo] + part[off + 128 + oo] +
                      part[off + 256 + oo] + part[off + 384 + oo] + b2s[oo];
            out[bb * On + oo] = fmaxf(v, 0.f);
        }
        b += 4 * grid;
    }

    // ---- tail: single batches ----
    while (b < Bn) {
        #pragma unroll
        for (int g = 0; g < 4; g++) { step(s, 0); s++; }
        __syncthreads();

        {
            const float4* hq = reinterpret_cast<const float4*>(hs + p * 64);
            float A0 = 0.f, A1 = 0.f;
            #pragma unroll
            for (int j = 0; j < 16; j++) {
                float4 hv = hq[j];
                A0 = fmaf(hv.x, w2r[4*j+0], A0);
                A1 = fmaf(hv.y, w2r[4*j+1], A1);
                A0 = fmaf(hv.z, w2r[4*j+2], A0);
                A1 = fmaf(hv.w, w2r[4*j+3], A1);
            }
            part[p * 128 + o] = A0 + A1;
        }
        __syncthreads();

        if (tid < On) {
            float v = part[tid] + part[128 + tid] + part[256 + tid] +
                      part[384 + tid] + b2s[tid];
            out[b * On + tid] = fmaxf(v, 0.f);
        }
        b += grid;
    }
    __pipeline_wait_prior(0);
}

extern "C" void kernel_launch(void* const* d_in, const int* in_sizes, int n_in,
                              void* d_out, int out_size)
{
    const float* in_ = (const float*)d_in[0];
    const float* W1  = (const float*)d_in[1];
    const float* b1  = (const float*)d_in[2];
    const float* W2  = (const float*)d_in[3];
    const float* b2  = (const float*)d_in[4];
    float* out       = (float*)d_out;

    int nsm = 0;
    if (cudaDeviceGetAttribute(&nsm, cudaDevAttrMultiProcessorCount, 0) != cudaSuccess
        || nsm <= 0) {
        nsm = 148;
    }

    cudaFuncSetAttribute(mlp_fused_kernel,
                         cudaFuncAttributeMaxDynamicSharedMemorySize, SMEM_BYTES);

    mlp_fused_kernel<<<nsm, THREADS, SMEM_BYTES>>>(in_, W1, b1, W2, b2, out);
}